// round 14
// baseline (speedup 1.0000x reference)
#include <cuda_runtime.h>
#include <cuda_bf16.h>
#include <cstdint>
#include <string.h>
#include <math.h>

namespace {

constexpr int B2   = 2;
constexpr int GHc  = 64, GWc = 64;
constexpr int NIN  = GHc * GWc;     // 4096
constexpr int Dc   = 384;
constexpr int Hc   = 12;
constexpr int HDc  = 32;
constexpr int QGc  = 22;
constexpr int NOUT = QGc * QGc;     // 484
constexpr int KSc  = 7, STc = 3, PADc = 3;
constexpr int DFF  = 4 * Dc;        // 1536
constexpr int KIM  = Dc * KSc * KSc; // 18816
constexpr int MR   = B2 * NOUT;     // 968
constexpr int KSPLITC = 6;
constexpr int KSUBC = KIM / KSPLITC; // 3136
constexpr int VSPLIT = 4;           // attn*V split-K
constexpr int QSPLIT = 4;           // q-proj split-K
constexpr int MSPLIT = 8;           // mlp2 split-K
constexpr float LNEPS = 1e-5f;
constexpr float EPSV  = 1.1920929e-07f;

constexpr int QROWS   = 8;
constexpr int NQB     = (NOUT + QROWS - 1) / QROWS;  // 61
constexpr int NCH     = 128;
constexpr int NCHUNKS = NIN / NCH;   // 32

constexpr long OUT_AQ = (long)B2 * NOUT * Dc;
constexpr long OUT_AK = OUT_AQ + (long)B2 * Hc * NOUT * NIN;

// ---------------- scratch ----------------
__device__ float g_part[KSPLITC * MR * Dc];
__device__ float g_kv[B2 * NIN * 2 * Dc];
__device__ float g_kt[B2 * Hc * HDc * NIN];     // K transposed [z][d][n]
__device__ float g_v [B2 * Hc * NIN * HDc];
__device__ float g_xout[MR * Dc];
__device__ float g_lin [QSPLIT * MR * Dc];      // q-proj split-K partials
__device__ float g_qr  [B2 * Hc * NOUT * HDc];
__device__ float g_upd [VSPLIT * MR * Dc];
__device__ float g_mlph[MR * DFF];
__device__ float g_mlpo[MSPLIT * MR * Dc];      // mlp2 split-K partials
__device__ float g_rcs[B2 * Hc * NIN];
__device__ float g_cspart[B2 * Hc * NQB * NIN]; // colsum partials (24 MB)

// bf16 hi/lo weights ([N][K] k-major rows)
__device__ __nv_bfloat16 g_cwh[Dc * KIM],  g_cwl[Dc * KIM];    // conv
__device__ __nv_bfloat16 g_kvwh[2*Dc*Dc],  g_kvwl[2*Dc*Dc];    // kv
__device__ __nv_bfloat16 g_qwh[Dc*Dc],     g_qwl[Dc*Dc];       // q
__device__ __nv_bfloat16 g_w1h[DFF*Dc],    g_w1l[DFF*Dc];      // mlp1
__device__ __nv_bfloat16 g_w2h[Dc*DFF],    g_w2l[Dc*DFF];      // mlp2

// ---------------- small helpers ----------------
__device__ __forceinline__ unsigned int b2u(__nv_bfloat162 v) {
    return *reinterpret_cast<unsigned int*>(&v);
}
__device__ __forceinline__ unsigned long long pk2(float lo, float hi) {
    unsigned long long r;
    asm("mov.b64 %0, {%1, %2};" : "=l"(r) : "f"(lo), "f"(hi));
    return r;
}
__device__ __forceinline__ unsigned long long ffma2(unsigned long long a,
                                                    unsigned long long b,
                                                    unsigned long long c) {
    unsigned long long d;
    asm("fma.rn.f32x2 %0, %1, %2, %3;" : "=l"(d) : "l"(a), "l"(b), "l"(c));
    return d;
}
__device__ __forceinline__ float2 upk(unsigned long long v) {
    float2 f;
    asm("mov.b64 {%0, %1}, %2;" : "=f"(f.x), "=f"(f.y) : "l"(v));
    return f;
}
__device__ __forceinline__ unsigned int smem_u32(const void* p) {
    unsigned int a;
    asm("{ .reg .u64 t; cvta.to.shared.u64 t, %1; cvt.u32.u64 %0, t; }"
        : "=r"(a) : "l"(p));
    return a;
}

// ---------------- reductions ----------------
__device__ __forceinline__ float warp_sum(float v) {
    #pragma unroll
    for (int o = 16; o; o >>= 1) v += __shfl_xor_sync(0xffffffffu, v, o);
    return v;
}
__device__ __forceinline__ float warp_max(float v) {
    #pragma unroll
    for (int o = 16; o; o >>= 1) v = fmaxf(v, __shfl_xor_sync(0xffffffffu, v, o));
    return v;
}
__device__ __forceinline__ float block_sum(float v, float* sbuf) {
    int lane = threadIdx.x & 31, wid = threadIdx.x >> 5;
    int nw = blockDim.x >> 5;
    v = warp_sum(v);
    if (lane == 0) sbuf[wid] = v;
    __syncthreads();
    if (wid == 0) {
        float r = (lane < nw) ? sbuf[lane] : 0.f;
        r = warp_sum(r);
        if (lane == 0) sbuf[0] = r;
    }
    __syncthreads();
    float r = sbuf[0];
    __syncthreads();
    return r;
}

// ---------------- mma.sync helpers (baseline PTX, sm_80+) ----------------
__device__ __forceinline__ void ldm4(unsigned int& r0, unsigned int& r1,
                                     unsigned int& r2, unsigned int& r3,
                                     unsigned int addr) {
    asm volatile("ldmatrix.sync.aligned.m8n8.x4.shared.b16 {%0,%1,%2,%3}, [%4];"
                 : "=r"(r0), "=r"(r1), "=r"(r2), "=r"(r3) : "r"(addr));
}
__device__ __forceinline__ void mma16816(float* c, const unsigned int* a,
                                         const unsigned int* b) {
    asm volatile(
        "mma.sync.aligned.m16n8k16.row.col.f32.bf16.bf16.f32 "
        "{%0,%1,%2,%3}, {%4,%5,%6,%7}, {%8,%9}, {%0,%1,%2,%3};"
        : "+f"(c[0]), "+f"(c[1]), "+f"(c[2]), "+f"(c[3])
        : "r"(a[0]), "r"(a[1]), "r"(a[2]), "r"(a[3]), "r"(b[0]), "r"(b[1]));
}

// ---------------- mma_gemm: bf16x3 HMMA GEMM, 128x128x32 tiles ------------
constexpr int PA = 40;   // smem pitch in halves (32 + 8 pad)

template<bool CONV>
__global__ __launch_bounds__(256, 1) void mma_gemm(
    const float* __restrict__ A,
    const __nv_bfloat16* __restrict__ Bh, const __nv_bfloat16* __restrict__ Bl,
    float* __restrict__ C,
    int M, int Kp, int lda, int ldb, int ldc,
    const float* __restrict__ bias, int act, long sCsplit)
{
    __shared__ __align__(16) __nv_bfloat16 sAh[128 * PA], sAl[128 * PA];
    __shared__ __align__(16) __nv_bfloat16 sBh[128 * PA], sBl[128 * PA];

    int tid = threadIdx.x, wid = tid >> 5, lane = tid & 31;
    int sp = blockIdx.z;
    int n0 = blockIdx.x * 128, m0 = blockIdx.y * 128;
    int ckb = sp * Kp;

    int warpM = wid >> 2, warpN = wid & 3;      // 2 x 4 warp grid
    int m0w = warpM * 64, n0w = warpN * 32;

    float acc[4][4][4];
    #pragma unroll
    for (int i = 0; i < 4; i++)
        #pragma unroll
        for (int j = 0; j < 4; j++)
            #pragma unroll
            for (int r = 0; r < 4; r++) acc[i][j][r] = 0.f;

    int lrow = lane & 15, lc8 = (lane >> 4) * 8;
    unsigned int aBh = smem_u32(sAh) + ((m0w + lrow) * PA + lc8) * 2;
    unsigned int aBl = smem_u32(sAl) + ((m0w + lrow) * PA + lc8) * 2;
    unsigned int bBh = smem_u32(sBh) + ((n0w + lrow) * PA + lc8) * 2;
    unsigned int bBl = smem_u32(sBl) + ((n0w + lrow) * PA + lc8) * 2;

    float4 aReg[4];
    uint4 bhReg[2], blReg[2];

    auto loadTile = [&](int k0) {
        #pragma unroll
        for (int i = 0; i < 4; i++) {
            int idx = tid + i * 256;
            int m  = idx >> 3;
            int q4 = (idx & 7) * 4;
            int gm = m0 + m;
            float4 v = make_float4(0.f, 0.f, 0.f, 0.f);
            if (CONV) {
                if (gm < M) {
                    int gk = ckb + k0 + q4;
                    int s = gk / Dc, din = gk - s * Dc;
                    int kh = s / KSc, kw = s - kh * KSc;
                    int b = gm / NOUT, n = gm - b * NOUT;
                    int oy = n / QGc, ox = n - oy * QGc;
                    int iy = oy * STc + kh - PADc, ix = ox * STc + kw - PADc;
                    if ((unsigned)iy < (unsigned)GHc && (unsigned)ix < (unsigned)GWc)
                        v = *reinterpret_cast<const float4*>(
                            &A[((long)b * NIN + iy * GWc + ix) * Dc + din]);
                }
            } else {
                if (gm < M)
                    v = *reinterpret_cast<const float4*>(
                        &A[(long)gm * lda + ckb + k0 + q4]);
            }
            aReg[i] = v;
        }
        #pragma unroll
        for (int i = 0; i < 2; i++) {
            int idx = tid + i * 256;
            int n  = idx >> 2;
            int kb = (idx & 3) * 8;
            long goff = (long)(n0 + n) * ldb + ckb + k0 + kb;
            bhReg[i] = *reinterpret_cast<const uint4*>(Bh + goff);
            blReg[i] = *reinterpret_cast<const uint4*>(Bl + goff);
        }
    };

    loadTile(0);
    int ntiles = Kp / 32;

    for (int kt = 0; kt < ntiles; kt++) {
        #pragma unroll
        for (int i = 0; i < 4; i++) {
            int idx = tid + i * 256;
            int m  = idx >> 3;
            int q4 = (idx & 7) * 4;
            float4 v = aReg[i];
            float hx = __bfloat162float(__float2bfloat16(v.x));
            float hy = __bfloat162float(__float2bfloat16(v.y));
            float hz = __bfloat162float(__float2bfloat16(v.z));
            float hw = __bfloat162float(__float2bfloat16(v.w));
            __nv_bfloat162 h01 = __floats2bfloat162_rn(v.x, v.y);
            __nv_bfloat162 h23 = __floats2bfloat162_rn(v.z, v.w);
            __nv_bfloat162 l01 = __floats2bfloat162_rn(v.x - hx, v.y - hy);
            __nv_bfloat162 l23 = __floats2bfloat162_rn(v.z - hz, v.w - hw);
            unsigned long long uh = (unsigned long long)b2u(h01) |
                ((unsigned long long)b2u(h23) << 32);
            unsigned long long ul = (unsigned long long)b2u(l01) |
                ((unsigned long long)b2u(l23) << 32);
            *reinterpret_cast<unsigned long long*>(&sAh[m * PA + q4]) = uh;
            *reinterpret_cast<unsigned long long*>(&sAl[m * PA + q4]) = ul;
        }
        #pragma unroll
        for (int i = 0; i < 2; i++) {
            int idx = tid + i * 256;
            int n  = idx >> 2;
            int kb = (idx & 3) * 8;
            *reinterpret_cast<uint4*>(&sBh[n * PA + kb]) = bhReg[i];
            *reinterpret_cast<uint4*>(&sBl[n * PA + kb]) = blReg[i];
        }
        __syncthreads();

        if (kt + 1 < ntiles) loadTile((kt + 1) * 32);

        #pragma unroll
        for (int ks = 0; ks < 2; ks++) {
            unsigned int aFh[4][4], aFl[4][4];
            unsigned int bFh[4][2], bFl[4][2];
            #pragma unroll
            for (int mi = 0; mi < 4; mi++) {
                unsigned int off = (mi * 16 * PA) * 2 + ks * 32;
                ldm4(aFh[mi][0], aFh[mi][1], aFh[mi][2], aFh[mi][3], aBh + off);
                ldm4(aFl[mi][0], aFl[mi][1], aFl[mi][2], aFl[mi][3], aBl + off);
            }
            #pragma unroll
            for (int ng = 0; ng < 2; ng++) {
                unsigned int off = (ng * 16 * PA) * 2 + ks * 32;
                unsigned int r0, r1, r2, r3;
                ldm4(r0, r1, r2, r3, bBh + off);
                bFh[2 * ng][0] = r0; bFh[2 * ng][1] = r2;
                bFh[2 * ng + 1][0] = r1; bFh[2 * ng + 1][1] = r3;
                ldm4(r0, r1, r2, r3, bBl + off);
                bFl[2 * ng][0] = r0; bFl[2 * ng][1] = r2;
                bFl[2 * ng + 1][0] = r1; bFl[2 * ng + 1][1] = r3;
            }
            #pragma unroll
            for (int mi = 0; mi < 4; mi++)
                #pragma unroll
                for (int ni = 0; ni < 4; ni++) {
                    mma16816(acc[mi][ni], aFh[mi], bFh[ni]);
                    mma16816(acc[mi][ni], aFh[mi], bFl[ni]);
                    mma16816(acc[mi][ni], aFl[mi], bFh[ni]);
                }
        }
        __syncthreads();
    }

    int lr = lane >> 2, lc = (lane & 3) * 2;
    float* Cb = C + (long)sp * sCsplit;
    bool doBias = (bias != nullptr) && (sp == 0);
    #pragma unroll
    for (int mi = 0; mi < 4; mi++) {
        int gmA = m0 + m0w + mi * 16 + lr;
        int gmB = gmA + 8;
        #pragma unroll
        for (int ni = 0; ni < 4; ni++) {
            int gn = n0 + n0w + ni * 8 + lc;
            float bx = 0.f, by = 0.f;
            if (doBias) { bx = bias[gn]; by = bias[gn + 1]; }
            if (gmA < M) {
                float px = acc[mi][ni][0] + bx;
                float py = acc[mi][ni][1] + by;
                if (act == 1) {
                    px = 0.5f * px * (1.f + erff(px * 0.70710678118654752f));
                    py = 0.5f * py * (1.f + erff(py * 0.70710678118654752f));
                }
                *reinterpret_cast<float2*>(&Cb[(long)gmA * ldc + gn]) =
                    make_float2(px, py);
            }
            if (gmB < M) {
                float px = acc[mi][ni][2] + bx;
                float py = acc[mi][ni][3] + by;
                if (act == 1) {
                    px = 0.5f * px * (1.f + erff(px * 0.70710678118654752f));
                    py = 0.5f * py * (1.f + erff(py * 0.70710678118654752f));
                }
                *reinterpret_cast<float2*>(&Cb[(long)gmB * ldc + gn]) =
                    make_float2(px, py);
            }
        }
    }
}

// ---------------- weight prep ----------------
__global__ void wprep_t(const float* __restrict__ w,
                        __nv_bfloat16* __restrict__ hi, __nv_bfloat16* __restrict__ lo,
                        int K0, int N0)
{
    __shared__ float t[32][33];
    int k0 = blockIdx.x * 32, n0 = blockIdx.y * 32;
    int tx = threadIdx.x, ty = threadIdx.y;
    #pragma unroll
    for (int i = ty; i < 32; i += 8)
        t[i][tx] = w[(long)(k0 + i) * N0 + n0 + tx];
    __syncthreads();
    #pragma unroll
    for (int i = ty; i < 32; i += 8) {
        float v = t[tx][i];
        long o = (long)(n0 + i) * K0 + k0 + tx;
        __nv_bfloat16 h = __float2bfloat16(v);
        hi[o] = h;
        lo[o] = __float2bfloat16(v - __bfloat162float(h));
    }
}

__global__ void wprep_conv(const float* __restrict__ w,
                           __nv_bfloat16* __restrict__ hi, __nv_bfloat16* __restrict__ lo)
{
    long i = (long)blockIdx.x * 256 + threadIdx.x;
    if (i >= (long)Dc * KIM) return;
    int n = (int)(i / KIM);
    int j = (int)(i - (long)n * KIM);
    int s = j / Dc, din = j - s * Dc;
    float v = w[(long)n * KIM + din * (KSc * KSc) + s];
    __nv_bfloat16 h = __float2bfloat16(v);
    hi[i] = h;
    lo[i] = __float2bfloat16(v - __bfloat162float(h));
}

// ---------------- legacy FFMA GEMM (attn*V: rcs scaling + aq stream) ------
template<int BM, int BN, int BK, int TM, int TN>
__global__ void fgemm2_kernel(
    const float* __restrict__ A, const float* __restrict__ B,
    float* __restrict__ C,
    int M, int K, int lda, int ldb, int ldc,
    long sAz, long sBz, long sCb, long sCh, int Hz,
    const float* __restrict__ rcol, long sRz,
    float* __restrict__ aq,
    int splitK, long sCsplit)
{
    constexpr int THREADS = (BM / TM) * (BN / TN);
    constexpr int AV = BM * BK / (4 * THREADS);
    constexpr int BV = BK * BN / (4 * THREADS);
    __shared__ __align__(16) float As2[BK][2 * BM];
    __shared__ __align__(16) float Bs[BK][BN];

    int zz = blockIdx.z;
    int sp = zz % splitK;
    int z  = zz / splitK;
    const float* Ap = A + (long)z * sAz + (long)sp * K;
    const float* Bp = B + (long)z * sBz + (long)sp * K * ldb;
    float* Cp = C + (long)(z / Hz) * sCb + (long)(z % Hz) * sCh + (long)sp * sCsplit;
    const float* rc = rcol + (long)z * sRz + (long)sp * K;
    float* aqp = aq ? aq + (long)z * sAz + (long)sp * K : nullptr;

    int tid = threadIdx.x;
    int m0 = blockIdx.y * BM, n0 = blockIdx.x * BN;
    int tcol = tid % (BN / TN), trow = tid / (BN / TN);

    unsigned long long acc[TM][TN / 2];
    #pragma unroll
    for (int i = 0; i < TM; i++)
        #pragma unroll
        for (int j = 0; j < TN / 2; j++) acc[i][j] = 0ull;

    float4 aReg[AV], bReg[BV], rReg[AV];

    auto loadTile = [&](int k0) {
        #pragma unroll
        for (int i = 0; i < AV; i++) {
            int idx = tid + i * THREADS;
            int m  = idx / (BK / 4);
            int kq = (idx % (BK / 4)) * 4;
            int gm = m0 + m;
            aReg[i] = make_float4(0.f, 0.f, 0.f, 0.f);
            if (gm < M)
                aReg[i] = *reinterpret_cast<const float4*>(&Ap[(long)gm * lda + k0 + kq]);
            rReg[i] = *reinterpret_cast<const float4*>(&rc[k0 + kq]);
        }
        #pragma unroll
        for (int i = 0; i < BV; i++) {
            int idx = tid + i * THREADS;
            int k  = idx / (BN / 4);
            int nq = (idx % (BN / 4)) * 4;
            bReg[i] = *reinterpret_cast<const float4*>(&Bp[(long)(k0 + k) * ldb + n0 + nq]);
        }
    };

    loadTile(0);
    int ntiles = K / BK;

    for (int kt = 0; kt < ntiles; kt++) {
        int k0 = kt * BK;
        #pragma unroll
        for (int i = 0; i < AV; i++) {
            int idx = tid + i * THREADS;
            int m  = idx / (BK / 4);
            int kq = (idx % (BK / 4)) * 4;
            float4 v = aReg[i];
            float4 r = rReg[i];
            v.x *= r.x; v.y *= r.y; v.z *= r.z; v.w *= r.w;
            if (aqp && (m0 + m) < M)
                *reinterpret_cast<float4*>(&aqp[(long)(m0 + m) * lda + k0 + kq]) = v;
            *reinterpret_cast<unsigned long long*>(&As2[kq + 0][2 * m]) = pk2(v.x, v.x);
            *reinterpret_cast<unsigned long long*>(&As2[kq + 1][2 * m]) = pk2(v.y, v.y);
            *reinterpret_cast<unsigned long long*>(&As2[kq + 2][2 * m]) = pk2(v.z, v.z);
            *reinterpret_cast<unsigned long long*>(&As2[kq + 3][2 * m]) = pk2(v.w, v.w);
        }
        #pragma unroll
        for (int i = 0; i < BV; i++) {
            int idx = tid + i * THREADS;
            int k  = idx / (BN / 4);
            int nq = (idx % (BN / 4)) * 4;
            *reinterpret_cast<float4*>(&Bs[k][nq]) = bReg[i];
        }
        __syncthreads();
        if (kt + 1 < ntiles) loadTile(k0 + BK);

        #pragma unroll
        for (int kk = 0; kk < BK; kk++) {
            unsigned long long ap[TM], bp[TN / 2];
            #pragma unroll
            for (int t = 0; t < TM / 2; t++) {
                ulonglong2 q = *reinterpret_cast<const ulonglong2*>(
                    &As2[kk][2 * (trow * TM + 2 * t)]);
                ap[2 * t] = q.x; ap[2 * t + 1] = q.y;
            }
            #pragma unroll
            for (int t = 0; t < TN / 4; t++) {
                ulonglong2 q = *reinterpret_cast<const ulonglong2*>(
                    &Bs[kk][tcol * TN + 4 * t]);
                bp[2 * t] = q.x; bp[2 * t + 1] = q.y;
            }
            #pragma unroll
            for (int i = 0; i < TM; i++)
                #pragma unroll
                for (int j = 0; j < TN / 2; j++)
                    acc[i][j] = ffma2(ap[i], bp[j], acc[i][j]);
        }
        __syncthreads();
    }

    #pragma unroll
    for (int i = 0; i < TM; i++) {
        int gm = m0 + trow * TM + i;
        if (gm >= M) continue;
        #pragma unroll
        for (int j = 0; j < TN / 2; j++) {
            int gn = n0 + tcol * TN + 2 * j;
            float2 p = upk(acc[i][j]);
            *reinterpret_cast<float2*>(&Cp[(long)gm * ldc + gn]) = p;
        }
    }
}

// ---------------- split-K reduce + bias + LN1 (conv) ----------------
__global__ void creduce_ln_kernel(const float* __restrict__ bias,
                                  const float* __restrict__ g,
                                  const float* __restrict__ b,
                                  float* __restrict__ out)
{
    __shared__ float sbuf[32];
    int m = blockIdx.x;
    int t = threadIdx.x;
    float s = bias[t];
    #pragma unroll
    for (int p = 0; p < KSPLITC; p++) s += g_part[p * (MR * Dc) + m * Dc + t];
    float mu = block_sum(s, sbuf) * (1.f / Dc);
    float c = s - mu;
    float var = block_sum(c * c, sbuf) * (1.f / Dc);
    out[(long)m * Dc + t] = c * rsqrtf(var + LNEPS) * g[t] + b[t];
}

// ---------------- LayerNorm (nparts pre-sum, optional residual, 2nd out) ---
__global__ void ln_kernel(const float* __restrict__ in, int nparts, long pstride,
                          const float* __restrict__ res,
                          const float* __restrict__ g, const float* __restrict__ b,
                          float* __restrict__ out, float* __restrict__ out2)
{
    __shared__ float sbuf[32];
    long row = blockIdx.x;
    int t = threadIdx.x;
    float v = 0.f;
    for (int p = 0; p < nparts; p++) v += in[p * pstride + row * Dc + t];
    float mu = block_sum(v, sbuf) * (1.f / Dc);
    float c = v - mu;
    float var = block_sum(c * c, sbuf) * (1.f / Dc);
    float o = c * rsqrtf(var + LNEPS) * g[t] + b[t];
    if (res) o += res[row * Dc + t];
    out[row * Dc + t] = o;
    if (out2) out2[row * Dc + t] = o;
}

// ---------------- rotary spatial embedding ----------------
__global__ void rose_kv_kernel(const float* __restrict__ freqs,
                               const float* __restrict__ temp)
{
    int idx = blockIdx.x * blockDim.x + threadIdx.x;
    if (idx >= B2 * Hc * NIN) return;
    int n  = idx % NIN;
    int bh = idx / NIN;
    int h  = bh % Hc;
    int b  = bh / Hc;
    float cy = (float)(n / GWc), cx = (float)(n % GWc);
    const float* f = freqs + h * 8;
    float cc[8], ss[8];
    #pragma unroll
    for (int j = 0; j < 8; j++) {
        float ang = ((j < 4) ? cy : cx) * f[j];
        cc[j] = cosf(ang); ss[j] = sinf(ang);
    }
    const float* src = g_kv + (long)(b * NIN + n) * (2 * Dc) + h * HDc;
    float xv[32];
    #pragma unroll
    for (int d = 0; d < 32; d++) xv[d] = src[d];
    float t = temp[0];
    float* kt = g_kt + (long)bh * HDc * NIN + n;
    #pragma unroll
    for (int j = 0; j < 8; j++) {
        float e = xv[2 * j], o = xv[2 * j + 1];
        kt[(long)(2 * j) * NIN]     = t * (e * cc[j] - o * ss[j]);
        kt[(long)(2 * j + 1) * NIN] = t * (e * ss[j] + o * cc[j]);
    }
    #pragma unroll
    for (int d = 16; d < 32; d++) kt[(long)d * NIN] = t * xv[d];
    const float* vs = src + Dc;
    float* vd = g_v + ((long)bh * NIN + n) * HDc;
    #pragma unroll
    for (int d = 0; d < 32; d++) vd[d] = vs[d];
}

// q rose; sums QSPLIT partials of the q-projection (bias already in part 0)
__global__ void rose_q_kernel(const float* __restrict__ freqs)
{
    int idx = blockIdx.x * blockDim.x + threadIdx.x;
    if (idx >= B2 * Hc * NOUT) return;
    int n  = idx % NOUT;
    int bh = idx / NOUT;
    int h  = bh % Hc;
    int b  = bh / Hc;
    float cy = (float)(n / QGc) * 3.0f, cx = (float)(n % QGc) * 3.0f;
    const float* f = freqs + h * 8;
    float cc[8], ss[8];
    #pragma unroll
    for (int j = 0; j < 8; j++) {
        float ang = ((j < 4) ? cy : cx) * f[j];
        cc[j] = cosf(ang); ss[j] = sinf(ang);
    }
    long base = (long)(b * NOUT + n) * Dc + h * HDc;
    float xv[32];
    #pragma unroll
    for (int d = 0; d < 32; d++) {
        float s = 0.f;
        #pragma unroll
        for (int p = 0; p < QSPLIT; p++)
            s += g_lin[(long)p * (MR * Dc) + base + d];
        xv[d] = s;
    }
    float* qd = g_qr + ((long)bh * NOUT + n) * HDc;
    #pragma unroll
    for (int j = 0; j < 8; j++) {
        float e = xv[2 * j], o = xv[2 * j + 1];
        qd[2 * j]     = e * cc[j] - o * ss[j];
        qd[2 * j + 1] = e * ss[j] + o * cc[j];
    }
    #pragma unroll
    for (int d = 16; d < 32; d++) qd[d] = xv[d];
}

// ---------------- fused QK^T + softmax + colsum partials ----------------
__global__ __launch_bounds__(256) void qk_softmax_kernel(
    const float* __restrict__ qr, const float* __restrict__ kt,
    float* __restrict__ attn)
{
    __shared__ __align__(16) float Ks[HDc][NCH];
    __shared__ float cs[NIN];                 // 16 KB column-sum accumulator
    int z = blockIdx.y;
    int tid = threadIdx.x, wid = tid >> 5, lane = tid & 31;
    int q = blockIdx.x * QROWS + wid;
    bool valid = (q < NOUT);
    const float* Kz = kt + (long)z * HDc * NIN;

    // zero colsum accumulator
    #pragma unroll
    for (int i = 0; i < NIN / 256; i++) cs[tid + i * 256] = 0.f;

    float Qr[HDc];
    if (valid) {
        const float* Qp = qr + ((long)z * NOUT + q) * HDc;
        #pragma unroll
        for (int i = 0; i < HDc / 4; i++) {
            float4 v = *reinterpret_cast<const float4*>(&Qp[4 * i]);
            Qr[4 * i] = v.x; Qr[4 * i + 1] = v.y;
            Qr[4 * i + 2] = v.z; Qr[4 * i + 3] = v.w;
        }
    }

    float4 pf[4];
    auto loadChunk = [&](int c) {
        #pragma unroll
        for (int i = 0; i < 4; i++) {
            int idx = tid + i * 256;
            int d = idx >> 5;
            int n = c * NCH + (idx & 31) * 4;
            pf[i] = *reinterpret_cast<const float4*>(&Kz[(long)d * NIN + n]);
        }
    };

    float4 S[NCHUNKS];
    loadChunk(0);
    #pragma unroll
    for (int c = 0; c < NCHUNKS; c++) {
        #pragma unroll
        for (int i = 0; i < 4; i++) {
            int idx = tid + i * 256;
            int d = idx >> 5;
            int n = (idx & 31) * 4;
            *reinterpret_cast<float4*>(&Ks[d][n]) = pf[i];
        }
        __syncthreads();
        if (c + 1 < NCHUNKS) loadChunk(c + 1);
        if (valid) {
            unsigned long long a01 = 0ull, a23 = 0ull;
            #pragma unroll
            for (int d = 0; d < HDc; d++) {
                ulonglong2 kv = *reinterpret_cast<const ulonglong2*>(&Ks[d][lane * 4]);
                unsigned long long qd = pk2(Qr[d], Qr[d]);
                a01 = ffma2(qd, kv.x, a01);
                a23 = ffma2(qd, kv.y, a23);
            }
            float2 p0 = upk(a01), p1 = upk(a23);
            S[c] = make_float4(p0.x, p0.y, p1.x, p1.y);
        }
        __syncthreads();
    }

    float inv = 0.f;
    if (valid) {
        float mx = -INFINITY;
        #pragma unroll
        for (int c = 0; c < NCHUNKS; c++)
            mx = fmaxf(mx, fmaxf(fmaxf(S[c].x, S[c].y), fmaxf(S[c].z, S[c].w)));
        mx = warp_max(mx);
        float s = 0.f;
        #pragma unroll
        for (int c = 0; c < NCHUNKS; c++) {
            S[c].x = __expf(S[c].x - mx); S[c].y = __expf(S[c].y - mx);
            S[c].z = __expf(S[c].z - mx); S[c].w = __expf(S[c].w - mx);
            s += S[c].x + S[c].y + S[c].z + S[c].w;
        }
        s = warp_sum(s);
        inv = 1.f / s;
        float* row = attn + ((long)z * NOUT + q) * NIN;
        #pragma unroll
        for (int c = 0; c < NCHUNKS; c++) {
            S[c].x *= inv; S[c].y *= inv; S[c].z *= inv; S[c].w *= inv;
            *reinterpret_cast<float4*>(&row[c * NCH + lane * 4]) = S[c];
        }
    }

    // deterministic column-sum accumulation: fixed warp order
    #pragma unroll
    for (int w = 0; w < QROWS; w++) {
        __syncthreads();
        if (wid == w && valid) {
            #pragma unroll
            for (int c = 0; c < NCHUNKS; c++) {
                int n = c * NCH + lane * 4;
                cs[n + 0] += S[c].x; cs[n + 1] += S[c].y;
                cs[n + 2] += S[c].z; cs[n + 3] += S[c].w;
            }
        }
    }
    __syncthreads();
    float* dst = &g_cspart[((long)z * NQB + blockIdx.x) * NIN];
    #pragma unroll
    for (int i = 0; i < NIN / (256 * 4); i++) {
        int n = (tid + i * 256) * 4;
        *reinterpret_cast<float4*>(&dst[n]) =
            *reinterpret_cast<const float4*>(&cs[n]);
    }
}

// ---------------- reduce colsum partials -> 1/(sum+eps) ----------------
__global__ void rcs_reduce_kernel()
{
    int z = blockIdx.y;
    int k = blockIdx.x * blockDim.x + threadIdx.x;
    const float* p = &g_cspart[(long)z * NQB * NIN + k];
    float s = 0.f;
    for (int j = 0; j < NQB; j++) s += p[(long)j * NIN];
    g_rcs[z * NIN + k] = 1.f / (s + EPSV);
}

} // anonymous namespace

extern "C" void kernel_launch(void* const* d_in, const int* in_sizes, int n_in,
                              void* d_out, int out_size)
{
    (void)in_sizes; (void)n_in; (void)out_size;
    const float* x       = (const float*)d_in[0];
    const float* conv_w  = (const float*)d_in[1];
    const float* conv_b  = (const float*)d_in[2];
    const float* kv_w    = (const float*)d_in[3];
    const float* kv_b    = (const float*)d_in[4];
    const float* q_w     = (const float*)d_in[5];
    const float* q_b     = (const float*)d_in[6];
    const float* mlp_w1  = (const float*)d_in[7];
    const float* mlp_b1  = (const float*)d_in[8];
    const float* mlp_w2  = (const float*)d_in[9];
    const float* mlp_b2  = (const float*)d_in[10];
    const float* g1      = (const float*)d_in[11];
    const float* b1      = (const float*)d_in[12];
    const float* g2      = (const float*)d_in[13];
    const float* b2      = (const float*)d_in[14];
    const float* g3      = (const float*)d_in[15];
    const float* b3      = (const float*)d_in[16];
    const float* temp    = (const float*)d_in[17];
    const float* rfreqs  = (const float*)d_in[18];

    float* out  = (float*)d_out;
    float* aq   = out + OUT_AQ;
    float* attn = out + OUT_AK;

    float *p_part, *p_kv, *p_kt, *p_v, *p_xout, *p_lin, *p_qr, *p_upd,
          *p_mlph, *p_mlpo, *p_rcs;
    __nv_bfloat16 *p_cwh, *p_cwl, *p_kvwh, *p_kvwl, *p_qwh, *p_qwl,
                  *p_w1h, *p_w1l, *p_w2h, *p_w2l;
    cudaGetSymbolAddress((void**)&p_part,  g_part);
    cudaGetSymbolAddress((void**)&p_kv,    g_kv);
    cudaGetSymbolAddress((void**)&p_kt,    g_kt);
    cudaGetSymbolAddress((void**)&p_v,     g_v);
    cudaGetSymbolAddress((void**)&p_xout,  g_xout);
    cudaGetSymbolAddress((void**)&p_lin,   g_lin);
    cudaGetSymbolAddress((void**)&p_qr,    g_qr);
    cudaGetSymbolAddress((void**)&p_upd,   g_upd);
    cudaGetSymbolAddress((void**)&p_mlph,  g_mlph);
    cudaGetSymbolAddress((void**)&p_mlpo,  g_mlpo);
    cudaGetSymbolAddress((void**)&p_rcs,   g_rcs);
    cudaGetSymbolAddress((void**)&p_cwh,   g_cwh);
    cudaGetSymbolAddress((void**)&p_cwl,   g_cwl);
    cudaGetSymbolAddress((void**)&p_kvwh,  g_kvwh);
    cudaGetSymbolAddress((void**)&p_kvwl,  g_kvwl);
    cudaGetSymbolAddress((void**)&p_qwh,   g_qwh);
    cudaGetSymbolAddress((void**)&p_qwl,   g_qwl);
    cudaGetSymbolAddress((void**)&p_w1h,   g_w1h);
    cudaGetSymbolAddress((void**)&p_w1l,   g_w1l);
    cudaGetSymbolAddress((void**)&p_w2h,   g_w2h);
    cudaGetSymbolAddress((void**)&p_w2l,   g_w2l);

    // ---- weight prep (bf16 hi/lo) ----
    wprep_conv<<<(unsigned)(((long)Dc * KIM + 255) / 256), 256>>>(conv_w, p_cwh, p_cwl);
    wprep_t<<<dim3(Dc / 32, (2 * Dc) / 32), dim3(32, 8)>>>(kv_w, p_kvwh, p_kvwl, Dc, 2 * Dc);
    wprep_t<<<dim3(Dc / 32, Dc / 32), dim3(32, 8)>>>(q_w, p_qwh, p_qwl, Dc, Dc);
    wprep_t<<<dim3(Dc / 32, DFF / 32), dim3(32, 8)>>>(mlp_w1, p_w1h, p_w1l, Dc, DFF);
    wprep_t<<<dim3(DFF / 32, Dc / 32), dim3(32, 8)>>>(mlp_w2, p_w2h, p_w2l, DFF, Dc);

    // ---- conv (HMMA, direct-from-x, split-K=6) + fused reduce+bias+LN1 ----
    mma_gemm<true><<<dim3(Dc / 128, 8, KSPLITC), 256>>>(
        x, p_cwh, p_cwl, p_part,
        MR, KSUBC, 0, KIM, Dc, nullptr, 0, (long)MR * Dc);
    creduce_ln_kernel<<<MR, Dc>>>(conv_b, g1, b1, p_xout);

    // ---- kv projection (HMMA) + rose ----
    mma_gemm<false><<<dim3((2 * Dc) / 128, (B2 * NIN) / 128, 1), 256>>>(
        x, p_kvwh, p_kvwl, p_kv,
        B2 * NIN, Dc, Dc, Dc, 2 * Dc, kv_b, 0, 0);
    rose_kv_kernel<<<(B2 * Hc * NIN + 127) / 128, 128>>>(rfreqs, temp);

    for (int it = 0; it < 3; it++) {
        bool last = (it == 2);
        // q projection (HMMA, split-K=4; bias in part 0) + rose sums parts
        mma_gemm<false><<<dim3(Dc / 128, 8, QSPLIT), 256>>>(
            p_xout, p_qwh, p_qwl, p_lin,
            MR, Dc / QSPLIT, Dc, Dc, Dc, q_b, 0, (long)MR * Dc);
        rose_q_kernel<<<(B2 * Hc * NOUT + 127) / 128, 128>>>(rfreqs);

        // fused QK^T + softmax + colsum partials; then partial reduce
        {
            dim3 g(NQB, B2 * Hc);
            qk_softmax_kernel<<<g, 256>>>(p_qr, p_kt, attn);
        }
        rcs_reduce_kernel<<<dim3(NIN / 256, B2 * Hc), 256>>>();

        // upd = (attn * rcs) * V, split-K=4; last iter streams attn_q
        {
            dim3 g(1, (NOUT + 63) / 64, B2 * Hc * VSPLIT);
            fgemm2_kernel<64, 32, 32, 4, 4><<<g, 128>>>(
                attn, p_v, p_upd,
                NOUT, NIN / VSPLIT, NIN, HDc, Dc,
                (long)NOUT * NIN, (long)NIN * HDc, (long)NOUT * Dc, HDc, Hc,
                p_rcs, NIN, last ? aq : nullptr,
                VSPLIT, (long)MR * Dc);
        }
        ln_kernel<<<MR, Dc>>>(p_upd, VSPLIT, (long)MR * Dc, p_xout, g2, b2,
                              p_xout, nullptr);

        // MLP (HMMA): w1 + GELU, then w2 split-K=8 reduced in LN
        mma_gemm<false><<<dim3(DFF / 128, 8, 1), 256>>>(
            p_xout, p_w1h, p_w1l, p_mlph,
            MR, Dc, Dc, Dc, DFF, mlp_b1, 1, 0);
        mma_gemm<false><<<dim3(Dc / 128, 8, MSPLIT), 256>>>(
            p_mlph, p_w2h, p_w2l, p_mlpo,
            MR, DFF / MSPLIT, DFF, DFF, Dc, mlp_b2, 0, (long)MR * Dc);
        ln_kernel<<<MR, Dc>>>(p_mlpo, MSPLIT, (long)MR * Dc, p_xout, g3, b3,
                              last ? out : p_xout, last ? p_xout : nullptr);
    }
}

// round 16
// speedup vs baseline: 1.7060x; 1.7060x over previous
#include <cuda_runtime.h>
#include <cuda_bf16.h>
#include <cstdint>
#include <string.h>
#include <math.h>

namespace {

constexpr int B2   = 2;
constexpr int GHc  = 64, GWc = 64;
constexpr int NIN  = GHc * GWc;     // 4096
constexpr int Dc   = 384;
constexpr int Hc   = 12;
constexpr int HDc  = 32;
constexpr int QGc  = 22;
constexpr int NOUT = QGc * QGc;     // 484
constexpr int KSc  = 7, STc = 3, PADc = 3;
constexpr int DFF  = 4 * Dc;        // 1536
constexpr int KIM  = Dc * KSc * KSc; // 18816
constexpr int MR   = B2 * NOUT;     // 968
constexpr int KSPLITC = 6;
constexpr int KSUBC = KIM / KSPLITC; // 3136
constexpr int VSPLIT = 4;           // attn*V split-K
constexpr int QSPLIT = 4;           // q-proj split-K
constexpr int MSPLIT = 8;           // mlp2 split-K
constexpr float LNEPS = 1e-5f;
constexpr float EPSV  = 1.1920929e-07f;

constexpr int QROWS   = 8;
constexpr int NCH     = 128;
constexpr int NCHUNKS = NIN / NCH;   // 32

constexpr long OUT_AQ = (long)B2 * NOUT * Dc;
constexpr long OUT_AK = OUT_AQ + (long)B2 * Hc * NOUT * NIN;

// ---------------- scratch ----------------
__device__ float g_part[KSPLITC * MR * Dc];
__device__ float g_kv[B2 * NIN * 2 * Dc];
__device__ float g_kt[B2 * Hc * HDc * NIN];     // K transposed [z][d][n]
__device__ float g_v [B2 * Hc * NIN * HDc];
__device__ float g_xout[MR * Dc];
__device__ float g_lin [QSPLIT * MR * Dc];      // q-proj split-K partials
__device__ float g_qr  [B2 * Hc * NOUT * HDc];
__device__ float g_upd [VSPLIT * MR * Dc];
__device__ float g_mlph[MR * DFF];
__device__ float g_mlpo[MSPLIT * MR * Dc];      // mlp2 split-K partials
__device__ float g_rcs[B2 * Hc * NIN];

// bf16 hi/lo weights ([N][K] k-major rows)
__device__ __nv_bfloat16 g_cwh[Dc * KIM],  g_cwl[Dc * KIM];    // conv
__device__ __nv_bfloat16 g_kvwh[2*Dc*Dc],  g_kvwl[2*Dc*Dc];    // kv
__device__ __nv_bfloat16 g_qwh[Dc*Dc],     g_qwl[Dc*Dc];       // q
__device__ __nv_bfloat16 g_w1h[DFF*Dc],    g_w1l[DFF*Dc];      // mlp1
__device__ __nv_bfloat16 g_w2h[Dc*DFF],    g_w2l[Dc*DFF];      // mlp2

// ---------------- small helpers ----------------
__device__ __forceinline__ unsigned int b2u(__nv_bfloat162 v) {
    return *reinterpret_cast<unsigned int*>(&v);
}
__device__ __forceinline__ unsigned long long pk2(float lo, float hi) {
    unsigned long long r;
    asm("mov.b64 %0, {%1, %2};" : "=l"(r) : "f"(lo), "f"(hi));
    return r;
}
__device__ __forceinline__ unsigned long long ffma2(unsigned long long a,
                                                    unsigned long long b,
                                                    unsigned long long c) {
    unsigned long long d;
    asm("fma.rn.f32x2 %0, %1, %2, %3;" : "=l"(d) : "l"(a), "l"(b), "l"(c));
    return d;
}
__device__ __forceinline__ float2 upk(unsigned long long v) {
    float2 f;
    asm("mov.b64 {%0, %1}, %2;" : "=f"(f.x), "=f"(f.y) : "l"(v));
    return f;
}
__device__ __forceinline__ unsigned int smem_u32(const void* p) {
    unsigned int a;
    asm("{ .reg .u64 t; cvta.to.shared.u64 t, %1; cvt.u32.u64 %0, t; }"
        : "=r"(a) : "l"(p));
    return a;
}

// ---------------- reductions ----------------
__device__ __forceinline__ float warp_sum(float v) {
    #pragma unroll
    for (int o = 16; o; o >>= 1) v += __shfl_xor_sync(0xffffffffu, v, o);
    return v;
}
__device__ __forceinline__ float warp_max(float v) {
    #pragma unroll
    for (int o = 16; o; o >>= 1) v = fmaxf(v, __shfl_xor_sync(0xffffffffu, v, o));
    return v;
}
__device__ __forceinline__ float block_sum(float v, float* sbuf) {
    int lane = threadIdx.x & 31, wid = threadIdx.x >> 5;
    int nw = blockDim.x >> 5;
    v = warp_sum(v);
    if (lane == 0) sbuf[wid] = v;
    __syncthreads();
    if (wid == 0) {
        float r = (lane < nw) ? sbuf[lane] : 0.f;
        r = warp_sum(r);
        if (lane == 0) sbuf[0] = r;
    }
    __syncthreads();
    float r = sbuf[0];
    __syncthreads();
    return r;
}

// ---------------- mma.sync helpers (baseline PTX, sm_80+) ----------------
__device__ __forceinline__ void ldm4(unsigned int& r0, unsigned int& r1,
                                     unsigned int& r2, unsigned int& r3,
                                     unsigned int addr) {
    asm volatile("ldmatrix.sync.aligned.m8n8.x4.shared.b16 {%0,%1,%2,%3}, [%4];"
                 : "=r"(r0), "=r"(r1), "=r"(r2), "=r"(r3) : "r"(addr));
}
__device__ __forceinline__ void mma16816(float* c, const unsigned int* a,
                                         const unsigned int* b) {
    asm volatile(
        "mma.sync.aligned.m16n8k16.row.col.f32.bf16.bf16.f32 "
        "{%0,%1,%2,%3}, {%4,%5,%6,%7}, {%8,%9}, {%0,%1,%2,%3};"
        : "+f"(c[0]), "+f"(c[1]), "+f"(c[2]), "+f"(c[3])
        : "r"(a[0]), "r"(a[1]), "r"(a[2]), "r"(a[3]), "r"(b[0]), "r"(b[1]));
}

// ---------------- mma_gemm: bf16x3 HMMA GEMM, 128x128x32 tiles ------------
constexpr int PA = 40;   // smem pitch in halves (32 + 8 pad)

template<bool CONV>
__global__ __launch_bounds__(256, 1) void mma_gemm(
    const float* __restrict__ A,
    const __nv_bfloat16* __restrict__ Bh, const __nv_bfloat16* __restrict__ Bl,
    float* __restrict__ C,
    int M, int Kp, int lda, int ldb, int ldc,
    const float* __restrict__ bias, int act, long sCsplit)
{
    __shared__ __align__(16) __nv_bfloat16 sAh[128 * PA], sAl[128 * PA];
    __shared__ __align__(16) __nv_bfloat16 sBh[128 * PA], sBl[128 * PA];

    int tid = threadIdx.x, wid = tid >> 5, lane = tid & 31;
    int sp = blockIdx.z;
    int n0 = blockIdx.x * 128, m0 = blockIdx.y * 128;
    int ckb = sp * Kp;

    int warpM = wid >> 2, warpN = wid & 3;      // 2 x 4 warp grid
    int m0w = warpM * 64, n0w = warpN * 32;

    float acc[4][4][4];
    #pragma unroll
    for (int i = 0; i < 4; i++)
        #pragma unroll
        for (int j = 0; j < 4; j++)
            #pragma unroll
            for (int r = 0; r < 4; r++) acc[i][j][r] = 0.f;

    int lrow = lane & 15, lc8 = (lane >> 4) * 8;
    unsigned int aBh = smem_u32(sAh) + ((m0w + lrow) * PA + lc8) * 2;
    unsigned int aBl = smem_u32(sAl) + ((m0w + lrow) * PA + lc8) * 2;
    unsigned int bBh = smem_u32(sBh) + ((n0w + lrow) * PA + lc8) * 2;
    unsigned int bBl = smem_u32(sBl) + ((n0w + lrow) * PA + lc8) * 2;

    float4 aReg[4];
    uint4 bhReg[2], blReg[2];

    auto loadTile = [&](int k0) {
        #pragma unroll
        for (int i = 0; i < 4; i++) {
            int idx = tid + i * 256;
            int m  = idx >> 3;
            int q4 = (idx & 7) * 4;
            int gm = m0 + m;
            float4 v = make_float4(0.f, 0.f, 0.f, 0.f);
            if (CONV) {
                if (gm < M) {
                    int gk = ckb + k0 + q4;
                    int s = gk / Dc, din = gk - s * Dc;
                    int kh = s / KSc, kw = s - kh * KSc;
                    int b = gm / NOUT, n = gm - b * NOUT;
                    int oy = n / QGc, ox = n - oy * QGc;
                    int iy = oy * STc + kh - PADc, ix = ox * STc + kw - PADc;
                    if ((unsigned)iy < (unsigned)GHc && (unsigned)ix < (unsigned)GWc)
                        v = *reinterpret_cast<const float4*>(
                            &A[((long)b * NIN + iy * GWc + ix) * Dc + din]);
                }
            } else {
                if (gm < M)
                    v = *reinterpret_cast<const float4*>(
                        &A[(long)gm * lda + ckb + k0 + q4]);
            }
            aReg[i] = v;
        }
        #pragma unroll
        for (int i = 0; i < 2; i++) {
            int idx = tid + i * 256;
            int n  = idx >> 2;
            int kb = (idx & 3) * 8;
            long goff = (long)(n0 + n) * ldb + ckb + k0 + kb;
            bhReg[i] = *reinterpret_cast<const uint4*>(Bh + goff);
            blReg[i] = *reinterpret_cast<const uint4*>(Bl + goff);
        }
    };

    loadTile(0);
    int ntiles = Kp / 32;

    for (int kt = 0; kt < ntiles; kt++) {
        #pragma unroll
        for (int i = 0; i < 4; i++) {
            int idx = tid + i * 256;
            int m  = idx >> 3;
            int q4 = (idx & 7) * 4;
            float4 v = aReg[i];
            float hx = __bfloat162float(__float2bfloat16(v.x));
            float hy = __bfloat162float(__float2bfloat16(v.y));
            float hz = __bfloat162float(__float2bfloat16(v.z));
            float hw = __bfloat162float(__float2bfloat16(v.w));
            __nv_bfloat162 h01 = __floats2bfloat162_rn(v.x, v.y);
            __nv_bfloat162 h23 = __floats2bfloat162_rn(v.z, v.w);
            __nv_bfloat162 l01 = __floats2bfloat162_rn(v.x - hx, v.y - hy);
            __nv_bfloat162 l23 = __floats2bfloat162_rn(v.z - hz, v.w - hw);
            unsigned long long uh = (unsigned long long)b2u(h01) |
                ((unsigned long long)b2u(h23) << 32);
            unsigned long long ul = (unsigned long long)b2u(l01) |
                ((unsigned long long)b2u(l23) << 32);
            *reinterpret_cast<unsigned long long*>(&sAh[m * PA + q4]) = uh;
            *reinterpret_cast<unsigned long long*>(&sAl[m * PA + q4]) = ul;
        }
        #pragma unroll
        for (int i = 0; i < 2; i++) {
            int idx = tid + i * 256;
            int n  = idx >> 2;
            int kb = (idx & 3) * 8;
            *reinterpret_cast<uint4*>(&sBh[n * PA + kb]) = bhReg[i];
            *reinterpret_cast<uint4*>(&sBl[n * PA + kb]) = blReg[i];
        }
        __syncthreads();

        if (kt + 1 < ntiles) loadTile((kt + 1) * 32);

        #pragma unroll
        for (int ks = 0; ks < 2; ks++) {
            unsigned int aFh[4][4], aFl[4][4];
            unsigned int bFh[4][2], bFl[4][2];
            #pragma unroll
            for (int mi = 0; mi < 4; mi++) {
                unsigned int off = (mi * 16 * PA) * 2 + ks * 32;
                ldm4(aFh[mi][0], aFh[mi][1], aFh[mi][2], aFh[mi][3], aBh + off);
                ldm4(aFl[mi][0], aFl[mi][1], aFl[mi][2], aFl[mi][3], aBl + off);
            }
            #pragma unroll
            for (int ng = 0; ng < 2; ng++) {
                unsigned int off = (ng * 16 * PA) * 2 + ks * 32;
                unsigned int r0, r1, r2, r3;
                ldm4(r0, r1, r2, r3, bBh + off);
                bFh[2 * ng][0] = r0; bFh[2 * ng][1] = r2;
                bFh[2 * ng + 1][0] = r1; bFh[2 * ng + 1][1] = r3;
                ldm4(r0, r1, r2, r3, bBl + off);
                bFl[2 * ng][0] = r0; bFl[2 * ng][1] = r2;
                bFl[2 * ng + 1][0] = r1; bFl[2 * ng + 1][1] = r3;
            }
            #pragma unroll
            for (int mi = 0; mi < 4; mi++)
                #pragma unroll
                for (int ni = 0; ni < 4; ni++) {
                    mma16816(acc[mi][ni], aFh[mi], bFh[ni]);
                    mma16816(acc[mi][ni], aFh[mi], bFl[ni]);
                    mma16816(acc[mi][ni], aFl[mi], bFh[ni]);
                }
        }
        __syncthreads();
    }

    int lr = lane >> 2, lc = (lane & 3) * 2;
    float* Cb = C + (long)sp * sCsplit;
    bool doBias = (bias != nullptr) && (sp == 0);
    #pragma unroll
    for (int mi = 0; mi < 4; mi++) {
        int gmA = m0 + m0w + mi * 16 + lr;
        int gmB = gmA + 8;
        #pragma unroll
        for (int ni = 0; ni < 4; ni++) {
            int gn = n0 + n0w + ni * 8 + lc;
            float bx = 0.f, by = 0.f;
            if (doBias) { bx = bias[gn]; by = bias[gn + 1]; }
            if (gmA < M) {
                float px = acc[mi][ni][0] + bx;
                float py = acc[mi][ni][1] + by;
                if (act == 1) {
                    px = 0.5f * px * (1.f + erff(px * 0.70710678118654752f));
                    py = 0.5f * py * (1.f + erff(py * 0.70710678118654752f));
                }
                *reinterpret_cast<float2*>(&Cb[(long)gmA * ldc + gn]) =
                    make_float2(px, py);
            }
            if (gmB < M) {
                float px = acc[mi][ni][2] + bx;
                float py = acc[mi][ni][3] + by;
                if (act == 1) {
                    px = 0.5f * px * (1.f + erff(px * 0.70710678118654752f));
                    py = 0.5f * py * (1.f + erff(py * 0.70710678118654752f));
                }
                *reinterpret_cast<float2*>(&Cb[(long)gmB * ldc + gn]) =
                    make_float2(px, py);
            }
        }
    }
}

// ---------------- weight prep ----------------
__global__ void wprep_t(const float* __restrict__ w,
                        __nv_bfloat16* __restrict__ hi, __nv_bfloat16* __restrict__ lo,
                        int K0, int N0)
{
    __shared__ float t[32][33];
    int k0 = blockIdx.x * 32, n0 = blockIdx.y * 32;
    int tx = threadIdx.x, ty = threadIdx.y;
    #pragma unroll
    for (int i = ty; i < 32; i += 8)
        t[i][tx] = w[(long)(k0 + i) * N0 + n0 + tx];
    __syncthreads();
    #pragma unroll
    for (int i = ty; i < 32; i += 8) {
        float v = t[tx][i];
        long o = (long)(n0 + i) * K0 + k0 + tx;
        __nv_bfloat16 h = __float2bfloat16(v);
        hi[o] = h;
        lo[o] = __float2bfloat16(v - __bfloat162float(h));
    }
}

__global__ void wprep_conv(const float* __restrict__ w,
                           __nv_bfloat16* __restrict__ hi, __nv_bfloat16* __restrict__ lo)
{
    long i = (long)blockIdx.x * 256 + threadIdx.x;
    if (i >= (long)Dc * KIM) return;
    int n = (int)(i / KIM);
    int j = (int)(i - (long)n * KIM);
    int s = j / Dc, din = j - s * Dc;
    float v = w[(long)n * KIM + din * (KSc * KSc) + s];
    __nv_bfloat16 h = __float2bfloat16(v);
    hi[i] = h;
    lo[i] = __float2bfloat16(v - __bfloat162float(h));
}

// ---------------- legacy FFMA GEMM (attn*V: rcs scaling + aq stream) ------
template<int BM, int BN, int BK, int TM, int TN>
__global__ void fgemm2_kernel(
    const float* __restrict__ A, const float* __restrict__ B,
    float* __restrict__ C,
    int M, int K, int lda, int ldb, int ldc,
    long sAz, long sBz, long sCb, long sCh, int Hz,
    const float* __restrict__ rcol, long sRz,
    float* __restrict__ aq,
    int splitK, long sCsplit)
{
    constexpr int THREADS = (BM / TM) * (BN / TN);
    constexpr int AV = BM * BK / (4 * THREADS);
    constexpr int BV = BK * BN / (4 * THREADS);
    __shared__ __align__(16) float As2[BK][2 * BM];
    __shared__ __align__(16) float Bs[BK][BN];

    int zz = blockIdx.z;
    int sp = zz % splitK;
    int z  = zz / splitK;
    const float* Ap = A + (long)z * sAz + (long)sp * K;
    const float* Bp = B + (long)z * sBz + (long)sp * K * ldb;
    float* Cp = C + (long)(z / Hz) * sCb + (long)(z % Hz) * sCh + (long)sp * sCsplit;
    const float* rc = rcol + (long)z * sRz + (long)sp * K;
    float* aqp = aq ? aq + (long)z * sAz + (long)sp * K : nullptr;

    int tid = threadIdx.x;
    int m0 = blockIdx.y * BM, n0 = blockIdx.x * BN;
    int tcol = tid % (BN / TN), trow = tid / (BN / TN);

    unsigned long long acc[TM][TN / 2];
    #pragma unroll
    for (int i = 0; i < TM; i++)
        #pragma unroll
        for (int j = 0; j < TN / 2; j++) acc[i][j] = 0ull;

    float4 aReg[AV], bReg[BV], rReg[AV];

    auto loadTile = [&](int k0) {
        #pragma unroll
        for (int i = 0; i < AV; i++) {
            int idx = tid + i * THREADS;
            int m  = idx / (BK / 4);
            int kq = (idx % (BK / 4)) * 4;
            int gm = m0 + m;
            aReg[i] = make_float4(0.f, 0.f, 0.f, 0.f);
            if (gm < M)
                aReg[i] = *reinterpret_cast<const float4*>(&Ap[(long)gm * lda + k0 + kq]);
            rReg[i] = *reinterpret_cast<const float4*>(&rc[k0 + kq]);
        }
        #pragma unroll
        for (int i = 0; i < BV; i++) {
            int idx = tid + i * THREADS;
            int k  = idx / (BN / 4);
            int nq = (idx % (BN / 4)) * 4;
            bReg[i] = *reinterpret_cast<const float4*>(&Bp[(long)(k0 + k) * ldb + n0 + nq]);
        }
    };

    loadTile(0);
    int ntiles = K / BK;

    for (int kt = 0; kt < ntiles; kt++) {
        int k0 = kt * BK;
        #pragma unroll
        for (int i = 0; i < AV; i++) {
            int idx = tid + i * THREADS;
            int m  = idx / (BK / 4);
            int kq = (idx % (BK / 4)) * 4;
            float4 v = aReg[i];
            float4 r = rReg[i];
            v.x *= r.x; v.y *= r.y; v.z *= r.z; v.w *= r.w;
            if (aqp && (m0 + m) < M)
                *reinterpret_cast<float4*>(&aqp[(long)(m0 + m) * lda + k0 + kq]) = v;
            *reinterpret_cast<unsigned long long*>(&As2[kq + 0][2 * m]) = pk2(v.x, v.x);
            *reinterpret_cast<unsigned long long*>(&As2[kq + 1][2 * m]) = pk2(v.y, v.y);
            *reinterpret_cast<unsigned long long*>(&As2[kq + 2][2 * m]) = pk2(v.z, v.z);
            *reinterpret_cast<unsigned long long*>(&As2[kq + 3][2 * m]) = pk2(v.w, v.w);
        }
        #pragma unroll
        for (int i = 0; i < BV; i++) {
            int idx = tid + i * THREADS;
            int k  = idx / (BN / 4);
            int nq = (idx % (BN / 4)) * 4;
            *reinterpret_cast<float4*>(&Bs[k][nq]) = bReg[i];
        }
        __syncthreads();
        if (kt + 1 < ntiles) loadTile(k0 + BK);

        #pragma unroll
        for (int kk = 0; kk < BK; kk++) {
            unsigned long long ap[TM], bp[TN / 2];
            #pragma unroll
            for (int t = 0; t < TM / 2; t++) {
                ulonglong2 q = *reinterpret_cast<const ulonglong2*>(
                    &As2[kk][2 * (trow * TM + 2 * t)]);
                ap[2 * t] = q.x; ap[2 * t + 1] = q.y;
            }
            #pragma unroll
            for (int t = 0; t < TN / 4; t++) {
                ulonglong2 q = *reinterpret_cast<const ulonglong2*>(
                    &Bs[kk][tcol * TN + 4 * t]);
                bp[2 * t] = q.x; bp[2 * t + 1] = q.y;
            }
            #pragma unroll
            for (int i = 0; i < TM; i++)
                #pragma unroll
                for (int j = 0; j < TN / 2; j++)
                    acc[i][j] = ffma2(ap[i], bp[j], acc[i][j]);
        }
        __syncthreads();
    }

    #pragma unroll
    for (int i = 0; i < TM; i++) {
        int gm = m0 + trow * TM + i;
        if (gm >= M) continue;
        #pragma unroll
        for (int j = 0; j < TN / 2; j++) {
            int gn = n0 + tcol * TN + 2 * j;
            float2 p = upk(acc[i][j]);
            *reinterpret_cast<float2*>(&Cp[(long)gm * ldc + gn]) = p;
        }
    }
}

// ---------------- split-K reduce + bias + LN1 (conv) ----------------
__global__ void creduce_ln_kernel(const float* __restrict__ bias,
                                  const float* __restrict__ g,
                                  const float* __restrict__ b,
                                  float* __restrict__ out)
{
    __shared__ float sbuf[32];
    int m = blockIdx.x;
    int t = threadIdx.x;
    float s = bias[t];
    #pragma unroll
    for (int p = 0; p < KSPLITC; p++) s += g_part[p * (MR * Dc) + m * Dc + t];
    float mu = block_sum(s, sbuf) * (1.f / Dc);
    float c = s - mu;
    float var = block_sum(c * c, sbuf) * (1.f / Dc);
    out[(long)m * Dc + t] = c * rsqrtf(var + LNEPS) * g[t] + b[t];
}

// ---------------- LayerNorm (nparts pre-sum, optional residual, 2nd out) ---
__global__ void ln_kernel(const float* __restrict__ in, int nparts, long pstride,
                          const float* __restrict__ res,
                          const float* __restrict__ g, const float* __restrict__ b,
                          float* __restrict__ out, float* __restrict__ out2)
{
    __shared__ float sbuf[32];
    long row = blockIdx.x;
    int t = threadIdx.x;
    float v = 0.f;
    for (int p = 0; p < nparts; p++) v += in[p * pstride + row * Dc + t];
    float mu = block_sum(v, sbuf) * (1.f / Dc);
    float c = v - mu;
    float var = block_sum(c * c, sbuf) * (1.f / Dc);
    float o = c * rsqrtf(var + LNEPS) * g[t] + b[t];
    if (res) o += res[row * Dc + t];
    out[row * Dc + t] = o;
    if (out2) out2[row * Dc + t] = o;
}

// ---------------- rotary spatial embedding ----------------
__global__ void rose_kv_kernel(const float* __restrict__ freqs,
                               const float* __restrict__ temp)
{
    int idx = blockIdx.x * blockDim.x + threadIdx.x;
    if (idx >= B2 * Hc * NIN) return;
    int n  = idx % NIN;
    int bh = idx / NIN;
    int h  = bh % Hc;
    int b  = bh / Hc;
    float cy = (float)(n / GWc), cx = (float)(n % GWc);
    const float* f = freqs + h * 8;
    float cc[8], ss[8];
    #pragma unroll
    for (int j = 0; j < 8; j++) {
        float ang = ((j < 4) ? cy : cx) * f[j];
        cc[j] = cosf(ang); ss[j] = sinf(ang);
    }
    const float* src = g_kv + (long)(b * NIN + n) * (2 * Dc) + h * HDc;
    float xv[32];
    #pragma unroll
    for (int d = 0; d < 32; d++) xv[d] = src[d];
    float t = temp[0];
    float* kt = g_kt + (long)bh * HDc * NIN + n;
    #pragma unroll
    for (int j = 0; j < 8; j++) {
        float e = xv[2 * j], o = xv[2 * j + 1];
        kt[(long)(2 * j) * NIN]     = t * (e * cc[j] - o * ss[j]);
        kt[(long)(2 * j + 1) * NIN] = t * (e * ss[j] + o * cc[j]);
    }
    #pragma unroll
    for (int d = 16; d < 32; d++) kt[(long)d * NIN] = t * xv[d];
    const float* vs = src + Dc;
    float* vd = g_v + ((long)bh * NIN + n) * HDc;
    #pragma unroll
    for (int d = 0; d < 32; d++) vd[d] = vs[d];
}

// q rose; sums QSPLIT partials of the q-projection (bias already in part 0)
__global__ void rose_q_kernel(const float* __restrict__ freqs)
{
    int idx = blockIdx.x * blockDim.x + threadIdx.x;
    if (idx >= B2 * Hc * NOUT) return;
    int n  = idx % NOUT;
    int bh = idx / NOUT;
    int h  = bh % Hc;
    int b  = bh / Hc;
    float cy = (float)(n / QGc) * 3.0f, cx = (float)(n % QGc) * 3.0f;
    const float* f = freqs + h * 8;
    float cc[8], ss[8];
    #pragma unroll
    for (int j = 0; j < 8; j++) {
        float ang = ((j < 4) ? cy : cx) * f[j];
        cc[j] = cosf(ang); ss[j] = sinf(ang);
    }
    long base = (long)(b * NOUT + n) * Dc + h * HDc;
    float xv[32];
    #pragma unroll
    for (int d = 0; d < 32; d++) {
        float s = 0.f;
        #pragma unroll
        for (int p = 0; p < QSPLIT; p++)
            s += g_lin[(long)p * (MR * Dc) + base + d];
        xv[d] = s;
    }
    float* qd = g_qr + ((long)bh * NOUT + n) * HDc;
    #pragma unroll
    for (int j = 0; j < 8; j++) {
        float e = xv[2 * j], o = xv[2 * j + 1];
        qd[2 * j]     = e * cc[j] - o * ss[j];
        qd[2 * j + 1] = e * ss[j] + o * cc[j];
    }
    #pragma unroll
    for (int d = 16; d < 32; d++) qd[d] = xv[d];
}

// ---------------- fused QK^T + softmax (warp per q-row) -------------------
__global__ __launch_bounds__(256) void qk_softmax_kernel(
    const float* __restrict__ qr, const float* __restrict__ kt,
    float* __restrict__ attn)
{
    __shared__ __align__(16) float Ks[HDc][NCH];
    int z = blockIdx.y;
    int tid = threadIdx.x, wid = tid >> 5, lane = tid & 31;
    int q = blockIdx.x * QROWS + wid;
    bool valid = (q < NOUT);
    const float* Kz = kt + (long)z * HDc * NIN;

    float Qr[HDc];
    if (valid) {
        const float* Qp = qr + ((long)z * NOUT + q) * HDc;
        #pragma unroll
        for (int i = 0; i < HDc / 4; i++) {
            float4 v = *reinterpret_cast<const float4*>(&Qp[4 * i]);
            Qr[4 * i] = v.x; Qr[4 * i + 1] = v.y;
            Qr[4 * i + 2] = v.z; Qr[4 * i + 3] = v.w;
        }
    }

    float4 pf[4];
    auto loadChunk = [&](int c) {
        #pragma unroll
        for (int i = 0; i < 4; i++) {
            int idx = tid + i * 256;
            int d = idx >> 5;
            int n = c * NCH + (idx & 31) * 4;
            pf[i] = *reinterpret_cast<const float4*>(&Kz[(long)d * NIN + n]);
        }
    };

    float4 S[NCHUNKS];
    loadChunk(0);
    #pragma unroll
    for (int c = 0; c < NCHUNKS; c++) {
        #pragma unroll
        for (int i = 0; i < 4; i++) {
            int idx = tid + i * 256;
            int d = idx >> 5;
            int n = (idx & 31) * 4;
            *reinterpret_cast<float4*>(&Ks[d][n]) = pf[i];
        }
        __syncthreads();
        if (c + 1 < NCHUNKS) loadChunk(c + 1);
        if (valid) {
            unsigned long long a01 = 0ull, a23 = 0ull;
            #pragma unroll
            for (int d = 0; d < HDc; d++) {
                ulonglong2 kv = *reinterpret_cast<const ulonglong2*>(&Ks[d][lane * 4]);
                unsigned long long qd = pk2(Qr[d], Qr[d]);
                a01 = ffma2(qd, kv.x, a01);
                a23 = ffma2(qd, kv.y, a23);
            }
            float2 p0 = upk(a01), p1 = upk(a23);
            S[c] = make_float4(p0.x, p0.y, p1.x, p1.y);
        }
        __syncthreads();
    }
    if (!valid) return;

    float mx = -INFINITY;
    #pragma unroll
    for (int c = 0; c < NCHUNKS; c++)
        mx = fmaxf(mx, fmaxf(fmaxf(S[c].x, S[c].y), fmaxf(S[c].z, S[c].w)));
    mx = warp_max(mx);
    float s = 0.f;
    #pragma unroll
    for (int c = 0; c < NCHUNKS; c++) {
        S[c].x = __expf(S[c].x - mx); S[c].y = __expf(S[c].y - mx);
        S[c].z = __expf(S[c].z - mx); S[c].w = __expf(S[c].w - mx);
        s += S[c].x + S[c].y + S[c].z + S[c].w;
    }
    s = warp_sum(s);
    float inv = 1.f / s;
    float* row = attn + ((long)z * NOUT + q) * NIN;
    #pragma unroll
    for (int c = 0; c < NCHUNKS; c++) {
        S[c].x *= inv; S[c].y *= inv; S[c].z *= inv; S[c].w *= inv;
        *reinterpret_cast<float4*>(&row[c * NCH + lane * 4]) = S[c];
    }
}

// ---------------- reciprocal column sums ----------------
__global__ void colsum_kernel(const float* __restrict__ attn)
{
    int z = blockIdx.y;
    int k = blockIdx.x * blockDim.x + threadIdx.x;
    const float* p = attn + (long)z * NOUT * NIN + k;
    float s = 0.f;
    for (int q = 0; q < NOUT; q++) s += p[(long)q * NIN];
    g_rcs[z * NIN + k] = 1.f / (s + EPSV);
}

} // anonymous namespace

extern "C" void kernel_launch(void* const* d_in, const int* in_sizes, int n_in,
                              void* d_out, int out_size)
{
    (void)in_sizes; (void)n_in; (void)out_size;
    const float* x       = (const float*)d_in[0];
    const float* conv_w  = (const float*)d_in[1];
    const float* conv_b  = (const float*)d_in[2];
    const float* kv_w    = (const float*)d_in[3];
    const float* kv_b    = (const float*)d_in[4];
    const float* q_w     = (const float*)d_in[5];
    const float* q_b     = (const float*)d_in[6];
    const float* mlp_w1  = (const float*)d_in[7];
    const float* mlp_b1  = (const float*)d_in[8];
    const float* mlp_w2  = (const float*)d_in[9];
    const float* mlp_b2  = (const float*)d_in[10];
    const float* g1      = (const float*)d_in[11];
    const float* b1      = (const float*)d_in[12];
    const float* g2      = (const float*)d_in[13];
    const float* b2      = (const float*)d_in[14];
    const float* g3      = (const float*)d_in[15];
    const float* b3      = (const float*)d_in[16];
    const float* temp    = (const float*)d_in[17];
    const float* rfreqs  = (const float*)d_in[18];

    float* out  = (float*)d_out;
    float* aq   = out + OUT_AQ;
    float* attn = out + OUT_AK;

    float *p_part, *p_kv, *p_kt, *p_v, *p_xout, *p_lin, *p_qr, *p_upd,
          *p_mlph, *p_mlpo, *p_rcs;
    __nv_bfloat16 *p_cwh, *p_cwl, *p_kvwh, *p_kvwl, *p_qwh, *p_qwl,
                  *p_w1h, *p_w1l, *p_w2h, *p_w2l;
    cudaGetSymbolAddress((void**)&p_part,  g_part);
    cudaGetSymbolAddress((void**)&p_kv,    g_kv);
    cudaGetSymbolAddress((void**)&p_kt,    g_kt);
    cudaGetSymbolAddress((void**)&p_v,     g_v);
    cudaGetSymbolAddress((void**)&p_xout,  g_xout);
    cudaGetSymbolAddress((void**)&p_lin,   g_lin);
    cudaGetSymbolAddress((void**)&p_qr,    g_qr);
    cudaGetSymbolAddress((void**)&p_upd,   g_upd);
    cudaGetSymbolAddress((void**)&p_mlph,  g_mlph);
    cudaGetSymbolAddress((void**)&p_mlpo,  g_mlpo);
    cudaGetSymbolAddress((void**)&p_rcs,   g_rcs);
    cudaGetSymbolAddress((void**)&p_cwh,   g_cwh);
    cudaGetSymbolAddress((void**)&p_cwl,   g_cwl);
    cudaGetSymbolAddress((void**)&p_kvwh,  g_kvwh);
    cudaGetSymbolAddress((void**)&p_kvwl,  g_kvwl);
    cudaGetSymbolAddress((void**)&p_qwh,   g_qwh);
    cudaGetSymbolAddress((void**)&p_qwl,   g_qwl);
    cudaGetSymbolAddress((void**)&p_w1h,   g_w1h);
    cudaGetSymbolAddress((void**)&p_w1l,   g_w1l);
    cudaGetSymbolAddress((void**)&p_w2h,   g_w2h);
    cudaGetSymbolAddress((void**)&p_w2l,   g_w2l);

    // ---- weight prep (bf16 hi/lo) ----
    wprep_conv<<<(unsigned)(((long)Dc * KIM + 255) / 256), 256>>>(conv_w, p_cwh, p_cwl);
    wprep_t<<<dim3(Dc / 32, (2 * Dc) / 32), dim3(32, 8)>>>(kv_w, p_kvwh, p_kvwl, Dc, 2 * Dc);
    wprep_t<<<dim3(Dc / 32, Dc / 32), dim3(32, 8)>>>(q_w, p_qwh, p_qwl, Dc, Dc);
    wprep_t<<<dim3(Dc / 32, DFF / 32), dim3(32, 8)>>>(mlp_w1, p_w1h, p_w1l, Dc, DFF);
    wprep_t<<<dim3(DFF / 32, Dc / 32), dim3(32, 8)>>>(mlp_w2, p_w2h, p_w2l, DFF, Dc);

    // ---- conv (HMMA, direct-from-x, split-K=6) + fused reduce+bias+LN1 ----
    mma_gemm<true><<<dim3(Dc / 128, 8, KSPLITC), 256>>>(
        x, p_cwh, p_cwl, p_part,
        MR, KSUBC, 0, KIM, Dc, nullptr, 0, (long)MR * Dc);
    creduce_ln_kernel<<<MR, Dc>>>(conv_b, g1, b1, p_xout);

    // ---- kv projection (HMMA) + rose ----
    mma_gemm<false><<<dim3((2 * Dc) / 128, (B2 * NIN) / 128, 1), 256>>>(
        x, p_kvwh, p_kvwl, p_kv,
        B2 * NIN, Dc, Dc, Dc, 2 * Dc, kv_b, 0, 0);
    rose_kv_kernel<<<(B2 * Hc * NIN + 127) / 128, 128>>>(rfreqs, temp);

    for (int it = 0; it < 3; it++) {
        bool last = (it == 2);
        // q projection (HMMA, split-K=4; bias in part 0) + rose sums parts
        mma_gemm<false><<<dim3(Dc / 128, 8, QSPLIT), 256>>>(
            p_xout, p_qwh, p_qwl, p_lin,
            MR, Dc / QSPLIT, Dc, Dc, Dc, q_b, 0, (long)MR * Dc);
        rose_q_kernel<<<(B2 * Hc * NOUT + 127) / 128, 128>>>(rfreqs);

        // fused QK^T + softmax (R13 version), then standalone colsum
        {
            dim3 g((NOUT + QROWS - 1) / QROWS, B2 * Hc);
            qk_softmax_kernel<<<g, 256>>>(p_qr, p_kt, attn);
        }
        colsum_kernel<<<dim3(NIN / 256, B2 * Hc), 256>>>(attn);

        // upd = (attn * rcs) * V, split-K=4; last iter streams attn_q
        {
            dim3 g(1, (NOUT + 63) / 64, B2 * Hc * VSPLIT);
            fgemm2_kernel<64, 32, 32, 4, 4><<<g, 128>>>(
                attn, p_v, p_upd,
                NOUT, NIN / VSPLIT, NIN, HDc, Dc,
                (long)NOUT * NIN, (long)NIN * HDc, (long)NOUT * Dc, HDc, Hc,
                p_rcs, NIN, last ? aq : nullptr,
                VSPLIT, (long)MR * Dc);
        }
        ln_kernel<<<MR, Dc>>>(p_upd, VSPLIT, (long)MR * Dc, p_xout, g2, b2,
                              p_xout, nullptr);

        // MLP (HMMA): w1 + GELU, then w2 split-K=8 reduced in LN
        mma_gemm<false><<<dim3(DFF / 128, 8, 1), 256>>>(
            p_xout, p_w1h, p_w1l, p_mlph,
            MR, Dc, Dc, Dc, DFF, mlp_b1, 1, 0);
        mma_gemm<false><<<dim3(Dc / 128, 8, MSPLIT), 256>>>(
            p_mlph, p_w2h, p_w2l, p_mlpo,
            MR, DFF / MSPLIT, DFF, DFF, Dc, mlp_b2, 0, (long)MR * Dc);
        ln_kernel<<<MR, Dc>>>(p_mlpo, MSPLIT, (long)MR * Dc, p_xout, g3, b3,
                              last ? out : p_xout, last ? p_xout : nullptr);
    }
}